// round 13
// baseline (speedup 1.0000x reference)
#include <cuda_runtime.h>
#include <cuda_bf16.h>
#include <cuda_fp16.h>
#include <math.h>
#include <stdint.h>

// Problem constants
#define BB 2
#define SS 2048
#define DD 1024
#define HH 16
#define DEP 64

// ---------------------------------------------------------------------------
// Scratch (device globals: no allocation allowed)
// ---------------------------------------------------------------------------
// split GEMM inputs: 0=q,1=k,2=v,3=ctx
__device__ __nv_bfloat16 g_ahi[4][BB * SS * DD];
__device__ __nv_bfloat16 g_alo[4][BB * SS * DD];
// transposed split weights: 0=wq,1=wk,2=wv,3=wo ; layout [n][k]
__device__ __nv_bfloat16 g_wthi[4][DD * DD];
__device__ __nv_bfloat16 g_wtlo[4][DD * DD];
// split projection outputs (Q,K,V)
__device__ __nv_bfloat16 g_phi[3][BB * SS * DD];
__device__ __nv_bfloat16 g_plo[3][BB * SS * DD];
// fp16 unnormalized attention scratch (numerators)
__device__ __half g_pf16[(size_t)BB * HH * SS * SS];

// ---------------------------------------------------------------------------
// PTX helpers (baseline ISA: ldmatrix + mma.sync + cp.async)
// ---------------------------------------------------------------------------
__device__ __forceinline__ uint32_t smem_u32(const void* p) {
    uint32_t a;
    asm("{ .reg .u64 t; cvta.to.shared.u64 t, %1; cvt.u32.u64 %0, t; }"
        : "=r"(a) : "l"(p));
    return a;
}

__device__ __forceinline__ void ldsm4(uint32_t addr, uint32_t r[4]) {
    asm volatile("ldmatrix.sync.aligned.m8n8.x4.shared.b16 {%0,%1,%2,%3}, [%4];"
                 : "=r"(r[0]), "=r"(r[1]), "=r"(r[2]), "=r"(r[3]) : "r"(addr));
}

__device__ __forceinline__ void ldsm2(uint32_t addr, uint32_t r[2]) {
    asm volatile("ldmatrix.sync.aligned.m8n8.x2.shared.b16 {%0,%1}, [%2];"
                 : "=r"(r[0]), "=r"(r[1]) : "r"(addr));
}

__device__ __forceinline__ void ldsm4t(uint32_t addr, uint32_t r[4]) {
    asm volatile("ldmatrix.sync.aligned.m8n8.x4.trans.shared.b16 {%0,%1,%2,%3}, [%4];"
                 : "=r"(r[0]), "=r"(r[1]), "=r"(r[2]), "=r"(r[3]) : "r"(addr));
}

__device__ __forceinline__ void mma16816(float c[4], const uint32_t a[4],
                                         const uint32_t b[2]) {
    asm volatile(
        "mma.sync.aligned.m16n8k16.row.col.f32.bf16.bf16.f32 "
        "{%0,%1,%2,%3}, {%4,%5,%6,%7}, {%8,%9}, {%0,%1,%2,%3};"
        : "+f"(c[0]), "+f"(c[1]), "+f"(c[2]), "+f"(c[3])
        : "r"(a[0]), "r"(a[1]), "r"(a[2]), "r"(a[3]), "r"(b[0]), "r"(b[1]));
}

__device__ __forceinline__ void cpa16(uint32_t s, const void* g) {
    asm volatile("cp.async.cg.shared.global [%0], [%1], 16;" :: "r"(s), "l"(g));
}
#define CP_COMMIT() asm volatile("cp.async.commit_group;" ::: "memory")
#define CP_WAIT(N) asm volatile("cp.async.wait_group %0;" :: "n"(N) : "memory")

__device__ __forceinline__ __nv_bfloat162 split2(float a, float b,
                                                 __nv_bfloat162& lo) {
    __nv_bfloat16 h0 = __float2bfloat16(a);
    __nv_bfloat16 h1 = __float2bfloat16(b);
    lo = __halves2bfloat162(__float2bfloat16(a - __bfloat162float(h0)),
                            __float2bfloat16(b - __bfloat162float(h1)));
    return __halves2bfloat162(h0, h1);
}

__device__ __forceinline__ void split2u(float a, float b, uint32_t& hi,
                                        uint32_t& lo) {
    __nv_bfloat162 l;
    __nv_bfloat162 h = split2(a, b, l);
    hi = *(uint32_t*)&h;
    lo = *(uint32_t*)&l;
}

// ---------------------------------------------------------------------------
// Split-precision conversion kernels (GEMM inputs)
// ---------------------------------------------------------------------------
__global__ void __launch_bounds__(256) split_qkv_kernel(const float* __restrict__ q,
                                                        const float* __restrict__ k,
                                                        const float* __restrict__ v) {
    const int z = blockIdx.y;
    const float* src = (z == 0) ? q : (z == 1) ? k : v;
    size_t i = (size_t)blockIdx.x * 256 + threadIdx.x;
    float4 x = ((const float4*)src)[i];
    __nv_bfloat162 l0, l1;
    __nv_bfloat162 h0 = split2(x.x, x.y, l0);
    __nv_bfloat162 h1 = split2(x.z, x.w, l1);
    ((__nv_bfloat162*)g_ahi[z])[2 * i + 0] = h0;
    ((__nv_bfloat162*)g_ahi[z])[2 * i + 1] = h1;
    ((__nv_bfloat162*)g_alo[z])[2 * i + 0] = l0;
    ((__nv_bfloat162*)g_alo[z])[2 * i + 1] = l1;
}

// Transpose + split weights: Wt[n][k] = W[k][n]
__global__ void __launch_bounds__(256) wt_split_kernel(const float* __restrict__ wq,
                                                       const float* __restrict__ wk,
                                                       const float* __restrict__ wv,
                                                       const float* __restrict__ wo) {
    const int z = blockIdx.z;
    const float* W = (z == 0) ? wq : (z == 1) ? wk : (z == 2) ? wv : wo;
    __shared__ float t[32][33];
    const int tx = threadIdx.x, ty = threadIdx.y;
    const int n0 = blockIdx.x * 32, k0 = blockIdx.y * 32;
#pragma unroll
    for (int i = 0; i < 4; i++)
        t[ty + 8 * i][tx] = W[(size_t)(k0 + ty + 8 * i) * DD + n0 + tx];
    __syncthreads();
#pragma unroll
    for (int i = 0; i < 4; i++) {
        int a = ty + 8 * i;
        float x = t[tx][a];
        __nv_bfloat16 h = __float2bfloat16(x);
        __nv_bfloat16 l = __float2bfloat16(x - __bfloat162float(h));
        g_wthi[z][(size_t)(n0 + a) * DD + k0 + tx] = h;
        g_wtlo[z][(size_t)(n0 + a) * DD + k0 + tx] = l;
    }
}

// ---------------------------------------------------------------------------
// mma.sync split-bf16 GEMM core: cp.async double-buffered, one barrier/iter
// ---------------------------------------------------------------------------
#define SROW 40
#define GB_AH 0
#define GB_AL 10240
#define GB_BH 20480
#define GB_BL 30720
#define GBUF_SZ 40960
#define GEMM_SMEM_BYTES (2 * GBUF_SZ)

template <bool BF16OUT>
__device__ __forceinline__ void gemm_mma_core(const __nv_bfloat16* __restrict__ Ahi,
                                              const __nv_bfloat16* __restrict__ Alo,
                                              const __nv_bfloat16* __restrict__ Bhi,
                                              const __nv_bfloat16* __restrict__ Blo,
                                              const float* __restrict__ bias,
                                              float* __restrict__ Cf,
                                              __nv_bfloat16* __restrict__ Chi,
                                              __nv_bfloat16* __restrict__ Clo) {
    extern __shared__ char gsm[];
    const uint32_t smb = smem_u32(gsm);

    const int tid = threadIdx.x;
    const int wid = tid >> 5, lane = tid & 31;
    const int mbase = blockIdx.y * 128;
    const int nbase = blockIdx.x * 128;
    const int wM = (wid >> 2) * 64;
    const int wN = (wid & 3) * 32;

    const uint4* A4h = (const uint4*)Ahi;
    const uint4* A4l = (const uint4*)Alo;
    const uint4* B4h = (const uint4*)Bhi;
    const uint4* B4l = (const uint4*)Blo;

    float acc[4][4][4];
#pragma unroll
    for (int mt = 0; mt < 4; mt++)
#pragma unroll
        for (int nt = 0; nt < 4; nt++)
#pragma unroll
            for (int e = 0; e < 4; e++) acc[mt][nt][e] = 0.0f;

    const int r0 = tid >> 2;
    const int c0 = tid & 3;

    auto prefetch = [&](uint32_t buf, int kc) {
#pragma unroll
        for (int i = 0; i < 2; i++) {
            int r = r0 + i * 64;
            size_t ga = (size_t)(mbase + r) * 128 + kc * 4 + c0;
            size_t gb = (size_t)(nbase + r) * 128 + kc * 4 + c0;
            uint32_t so = (uint32_t)(r * (SROW * 2) + c0 * 16);
            cpa16(buf + GB_AH + so, &A4h[ga]);
            cpa16(buf + GB_AL + so, &A4l[ga]);
            cpa16(buf + GB_BH + so, &B4h[gb]);
            cpa16(buf + GB_BL + so, &B4l[gb]);
        }
    };

    prefetch(smb, 0);
    CP_COMMIT();

    for (int kc = 0; kc < 32; kc++) {
        CP_WAIT(0);
        __syncthreads();
        if (kc < 31) {
            prefetch(smb + ((kc + 1) & 1) * GBUF_SZ, kc + 1);
            CP_COMMIT();
        }
        const uint32_t buf = smb + (kc & 1) * GBUF_SZ;

#pragma unroll
        for (int s = 0; s < 2; s++) {
            uint32_t ah[4][4], al[4][4];
#pragma unroll
            for (int mt = 0; mt < 4; mt++) {
                uint32_t off = (uint32_t)((wM + mt * 16 + (lane & 15)) * (SROW * 2) +
                                          (s * 16 + (lane >> 4) * 8) * 2);
                ldsm4(buf + GB_AH + off, ah[mt]);
                ldsm4(buf + GB_AL + off, al[mt]);
            }
            uint32_t bh[4][2], bl[4][2];
#pragma unroll
            for (int nt = 0; nt < 4; nt++) {
                uint32_t off = (uint32_t)((wN + nt * 8 + (lane & 7)) * (SROW * 2) +
                                          (s * 16 + (lane & 8)) * 2);
                ldsm2(buf + GB_BH + off, bh[nt]);
                ldsm2(buf + GB_BL + off, bl[nt]);
            }
#pragma unroll
            for (int mt = 0; mt < 4; mt++)
#pragma unroll
                for (int nt = 0; nt < 4; nt++) {
                    mma16816(acc[mt][nt], ah[mt], bh[nt]);
                    mma16816(acc[mt][nt], ah[mt], bl[nt]);
                    mma16816(acc[mt][nt], al[mt], bh[nt]);
                }
        }
    }

#pragma unroll
    for (int mt = 0; mt < 4; mt++)
#pragma unroll
        for (int nt = 0; nt < 4; nt++) {
            int row = mbase + wM + mt * 16 + (lane >> 2);
            int col = nbase + wN + nt * 8 + (lane & 3) * 2;
            float b0 = bias[col], b1 = bias[col + 1];
            float v00 = acc[mt][nt][0] + b0, v01 = acc[mt][nt][1] + b1;
            float v10 = acc[mt][nt][2] + b0, v11 = acc[mt][nt][3] + b1;
            if (BF16OUT) {
                __nv_bfloat162 l0, l1;
                __nv_bfloat162 h0 = split2(v00, v01, l0);
                __nv_bfloat162 h1 = split2(v10, v11, l1);
                *(__nv_bfloat162*)&Chi[(size_t)row * 1024 + col] = h0;
                *(__nv_bfloat162*)&Clo[(size_t)row * 1024 + col] = l0;
                *(__nv_bfloat162*)&Chi[(size_t)(row + 8) * 1024 + col] = h1;
                *(__nv_bfloat162*)&Clo[(size_t)(row + 8) * 1024 + col] = l1;
            } else {
                *(float2*)&Cf[(size_t)row * 1024 + col] = make_float2(v00, v01);
                *(float2*)&Cf[(size_t)(row + 8) * 1024 + col] = make_float2(v10, v11);
            }
        }
}

__global__ void __launch_bounds__(256) mma_gemm_qkv_kernel(const float* __restrict__ bq,
                                                           const float* __restrict__ bk,
                                                           const float* __restrict__ bv) {
    const int z = blockIdx.z;
    const float* bias = (z == 0) ? bq : (z == 1) ? bk : bv;
    gemm_mma_core<true>(g_ahi[z], g_alo[z], g_wthi[z], g_wtlo[z], bias, nullptr,
                        g_phi[z], g_plo[z]);
}

__global__ void __launch_bounds__(256) mma_gemm_o_kernel(const float* __restrict__ bo,
                                                         float* __restrict__ out) {
    gemm_mma_core<false>(g_ahi[3], g_alo[3], g_wthi[3], g_wtlo[3], bo, out,
                         nullptr, nullptr);
}

// ---------------------------------------------------------------------------
// FA2-style HMMA attention (R11 core) + fp16 p-scratch:
//  - p written as half2 to g_pf16 (256 MB instead of 512 MB fp32)
//  - fused tail reads fp16 scratch, writes fp32 normalized attn ONCE
// ---------------------------------------------------------------------------
#define SRB 144                         // 64 bf16 + 8 pad per row
#define O_Q 0
#define BUF_BASE 18432
#define BUF_SZ 36864
#define BK_H 0
#define BK_L 9216
#define BV_H 18432
#define BV_L 27648
#define O_RS (BUF_BASE + 2 * BUF_SZ)
#define ATTN_SMEM_BYTES (O_RS + 512)

__device__ __forceinline__ void load_tile128(char* sm, uint32_t off,
                                             const __nv_bfloat16* g, int tid) {
    const uint4* g4 = (const uint4*)g;
#pragma unroll
    for (int i = 0; i < 4; i++) {
        int idx = tid + i * 256;
        int r = idx >> 3, c8 = idx & 7;
        *(uint4*)(sm + off + r * SRB + c8 * 16) = g4[(size_t)r * 128 + c8];
    }
}

__device__ __forceinline__ void prefetch_kv(uint32_t bufb,
                                            const __nv_bfloat16* Kh,
                                            const __nv_bfloat16* Kl,
                                            const __nv_bfloat16* Vh,
                                            const __nv_bfloat16* Vl, int tid) {
#pragma unroll
    for (int i = 0; i < 2; i++) {
        int idx = tid + i * 256;
        int r = idx >> 3, c8 = idx & 7;
        uint32_t so = (uint32_t)(r * SRB + c8 * 16);
        size_t go = (size_t)r * 1024 + c8 * 8;
        cpa16(bufb + BK_H + so, Kh + go);
        cpa16(bufb + BK_L + so, Kl + go);
        cpa16(bufb + BV_H + so, Vh + go);
        cpa16(bufb + BV_L + so, Vl + go);
    }
}

__global__ void __launch_bounds__(256, 2) attn_mma_kernel(
    const float* __restrict__ mask, float* __restrict__ attn, int write_attn) {
    extern __shared__ char sm[];
    const uint32_t smb = smem_u32(sm);
    float* rowsum = (float*)(sm + O_RS);

    const int tid = threadIdx.x;
    const int wid = tid >> 5, lane = tid & 31;
    const int bh = blockIdx.y;
    const int b = bh / HH, h = bh % HH;
    const int q0g = blockIdx.x * 128;
    const int qrow = wid * 16;

    const size_t hoff = (size_t)h * DEP;
    const float* maskrow = mask + (size_t)b * SS;

    // prefetch key tile 0
    {
        const size_t koff = (size_t)b * SS * DD + hoff;
        prefetch_kv(smb + BUF_BASE, g_phi[1] + koff, g_plo[1] + koff,
                    g_phi[2] + koff, g_plo[2] + koff, tid);
        CP_COMMIT();
    }

    // stage Q_hi and hoist A-fragments
    {
        const size_t qoff = ((size_t)b * SS + q0g) * DD + hoff;
        load_tile128(sm, O_Q, g_phi[0] + qoff, tid);
    }
    __syncthreads();

    uint32_t Qah[4][4];
#pragma unroll
    for (int s = 0; s < 4; s++) {
        uint32_t off = (uint32_t)((qrow + (lane & 15)) * SRB +
                                  (s * 16 + (lane >> 4) * 8) * 2);
        ldsm4(smb + O_Q + off, Qah[s]);
    }

    float ctx[8][4];
#pragma unroll
    for (int j = 0; j < 8; j++)
#pragma unroll
        for (int e = 0; e < 4; e++) ctx[j][e] = 0.0f;

    float rs0 = 0.0f, rs1 = 0.0f;

    for (int kt = 0; kt < 32; kt++) {
        if (kt < 31) {
            const size_t koff =
                ((size_t)b * SS + (kt + 1) * 64) * DD + hoff;
            uint32_t bufn = smb + BUF_BASE + ((kt + 1) & 1) * BUF_SZ;
            prefetch_kv(bufn, g_phi[1] + koff, g_plo[1] + koff,
                        g_phi[2] + koff, g_plo[2] + koff, tid);
            CP_COMMIT();
            CP_WAIT(1);
        } else {
            CP_WAIT(0);
        }
        __syncthreads();
        const uint32_t buf = smb + BUF_BASE + (kt & 1) * BUF_SZ;

        // ---- S = Q K^T over 64 keys (2-MMA: qh*kh + qh*kl) ----
        float accS[8][4];
#pragma unroll
        for (int j = 0; j < 8; j++)
#pragma unroll
            for (int e = 0; e < 4; e++) accS[j][e] = 0.0f;

#pragma unroll
        for (int s = 0; s < 4; s++) {
            const uint32_t brow = (lane & 7) + ((lane >> 4) << 3);
            const uint32_t bcol = (s * 16 + ((lane >> 3) & 1) * 8) * 2;
#pragma unroll
            for (int jp = 0; jp < 4; jp++) {
                uint32_t kb[4], kl[4];
                uint32_t off = (uint32_t)((16 * jp + brow) * SRB + bcol);
                ldsm4(buf + BK_H + off, kb);
                ldsm4(buf + BK_L + off, kl);
                mma16816(accS[2 * jp], Qah[s], kb);
                mma16816(accS[2 * jp], Qah[s], kl);
                mma16816(accS[2 * jp + 1], Qah[s], kb + 2);
                mma16816(accS[2 * jp + 1], Qah[s], kl + 2);
            }
        }

        // ---- interleaved: exp/split for 16-key group s, then PV MMAs ----
        const int rowl = qrow + (lane >> 2);
#pragma unroll
        for (int s = 0; s < 4; s++) {
            uint32_t pah[4], pal[4];
#pragma unroll
            for (int jj = 0; jj < 2; jj++) {
                const int j = 2 * s + jj;
                const int coll = 8 * j + (lane & 3) * 2;
                const int gcol = kt * 64 + coll;
                float m0 = __ldg(&maskrow[gcol]) * -1e9f;
                float m1 = __ldg(&maskrow[gcol + 1]) * -1e9f;
                float p00 = __expf(accS[j][0] * 0.125f + m0);
                float p01 = __expf(accS[j][1] * 0.125f + m1);
                float p10 = __expf(accS[j][2] * 0.125f + m0);
                float p11 = __expf(accS[j][3] * 0.125f + m1);
                rs0 += p00 + p01;
                rs1 += p10 + p11;
                if (write_attn) {
                    __half* prow = g_pf16 + (size_t)bh * SS * SS +
                                   (size_t)(q0g + rowl) * SS + gcol;
                    *(__half2*)prow = __floats2half2_rn(p00, p01);
                    *(__half2*)(prow + 8 * SS) = __floats2half2_rn(p10, p11);
                }
                const int o = jj * 2;
                split2u(p00, p01, pah[o], pal[o]);
                split2u(p10, p11, pah[o + 1], pal[o + 1]);
            }
            const uint32_t vrow = 16 * s + (lane & 15);
#pragma unroll
            for (int jp = 0; jp < 4; jp++) {
                uint32_t vb[4], vl[4];
                uint32_t off = (uint32_t)(vrow * SRB +
                                          (16 * jp + ((lane >> 4) << 3)) * 2);
                ldsm4t(buf + BV_H + off, vb);
                ldsm4t(buf + BV_L + off, vl);
                mma16816(ctx[2 * jp], pah, vb);
                mma16816(ctx[2 * jp], pah, vl);
                mma16816(ctx[2 * jp], pal, vb);
                mma16816(ctx[2 * jp + 1], pah, vb + 2);
                mma16816(ctx[2 * jp + 1], pah, vl + 2);
                mma16816(ctx[2 * jp + 1], pal, vb + 2);
            }
        }
        __syncthreads();  // all warps done with buf before overwrite
    }

    // rowsums: warp-local reduce (each warp owns distinct rows)
    rs0 += __shfl_xor_sync(0xffffffffu, rs0, 1);
    rs0 += __shfl_xor_sync(0xffffffffu, rs0, 2);
    rs1 += __shfl_xor_sync(0xffffffffu, rs1, 1);
    rs1 += __shfl_xor_sync(0xffffffffu, rs1, 2);
    if ((lane & 3) == 0) {
        rowsum[qrow + (lane >> 2)] = rs0;
        rowsum[qrow + 8 + (lane >> 2)] = rs1;
    }
    __syncthreads();  // rowsum complete + p-writes visible block-wide

    // normalize ctx, split, store as O-GEMM input
    const int rowl = qrow + (lane >> 2);
    const float inv0 = 1.0f / rowsum[rowl];
    const float inv1 = 1.0f / rowsum[rowl + 8];
#pragma unroll
    for (int j = 0; j < 8; j++) {
        const int col = 8 * j + (lane & 3) * 2;
        size_t gi = ((size_t)b * SS + q0g + rowl) * DD + hoff + col;
        __nv_bfloat162 l0, l1;
        __nv_bfloat162 h0 = split2(ctx[j][0] * inv0, ctx[j][1] * inv0, l0);
        __nv_bfloat162 h1 = split2(ctx[j][2] * inv1, ctx[j][3] * inv1, l1);
        *(__nv_bfloat162*)&g_ahi[3][gi] = h0;
        *(__nv_bfloat162*)&g_alo[3][gi] = l0;
        *(__nv_bfloat162*)&g_ahi[3][gi + 8 * DD] = h1;
        *(__nv_bfloat162*)&g_alo[3][gi + 8 * DD] = l1;
    }

    // tail: read fp16 p, write fp32 normalized attn ONCE (coalesced)
    if (write_attn) {
#pragma unroll 1
        for (int r = 0; r < 16; r++) {
            const int row = qrow + r;
            const float inv = 1.0f / rowsum[row];
            const __half2* prow =
                (const __half2*)(g_pf16 + (size_t)bh * SS * SS +
                                 (size_t)(q0g + row) * SS);
            float2* arow = (float2*)(attn + (size_t)bh * SS * SS +
                                     (size_t)(q0g + row) * SS);
#pragma unroll
            for (int c = 0; c < 32; c++) {
                float2 v = __half22float2(prow[lane + c * 32]);
                v.x *= inv;
                v.y *= inv;
                arow[lane + c * 32] = v;
            }
        }
    }
}

// ---------------------------------------------------------------------------
// kernel_launch
// ---------------------------------------------------------------------------
extern "C" void kernel_launch(void* const* d_in, const int* in_sizes, int n_in,
                              void* d_out, int out_size) {
    const float* q = (const float*)d_in[0];
    const float* k = (const float*)d_in[1];
    const float* v = (const float*)d_in[2];
    const float* mask = (const float*)d_in[3];
    const float* wq = (const float*)d_in[4];
    const float* bq = (const float*)d_in[5];
    const float* wk = (const float*)d_in[6];
    const float* bk = (const float*)d_in[7];
    const float* wv = (const float*)d_in[8];
    const float* bv = (const float*)d_in[9];
    const float* wo = (const float*)d_in[10];
    const float* bo = (const float*)d_in[11];

    float* out = (float*)d_out;
    const long long out_elems = (long long)BB * SS * DD;
    const long long need = out_elems + (long long)BB * HH * SS * SS;
    int write_attn = ((long long)out_size >= need) ? 1 : 0;
    float* attn = out + (size_t)out_elems;

    cudaFuncSetAttribute(attn_mma_kernel,
                         cudaFuncAttributeMaxDynamicSharedMemorySize,
                         ATTN_SMEM_BYTES);
    cudaFuncSetAttribute(mma_gemm_qkv_kernel,
                         cudaFuncAttributeMaxDynamicSharedMemorySize,
                         GEMM_SMEM_BYTES);
    cudaFuncSetAttribute(mma_gemm_o_kernel,
                         cudaFuncAttributeMaxDynamicSharedMemorySize,
                         GEMM_SMEM_BYTES);

    // 1. split inputs + weights
    split_qkv_kernel<<<dim3(BB * SS * DD / 4 / 256, 3), 256>>>(q, k, v);
    wt_split_kernel<<<dim3(32, 32, 4), dim3(32, 8)>>>(wq, wk, wv, wo);

    // 2. Q/K/V projections on HMMA (cp.async pipelined) -> split bf16 outputs
    mma_gemm_qkv_kernel<<<dim3(8, 32, 3), 256, GEMM_SMEM_BYTES>>>(bq, bk, bv);

    // 3. FA2-style HMMA attention (fp16 p-scratch + fused norm + split ctx)
    attn_mma_kernel<<<dim3(SS / 128, BB * HH), 256, ATTN_SMEM_BYTES>>>(
        mask, attn, write_attn);

    // 4. output projection on HMMA
    mma_gemm_o_kernel<<<dim3(8, 32), 256, GEMM_SMEM_BYTES>>>(bo, out);
}

// round 14
// speedup vs baseline: 1.4400x; 1.4400x over previous
#include <cuda_runtime.h>
#include <cuda_bf16.h>
#include <math.h>
#include <stdint.h>

// Problem constants
#define BB 2
#define SS 2048
#define DD 1024
#define HH 16
#define DEP 64

// ---------------------------------------------------------------------------
// Scratch (device globals: no allocation allowed)
// ---------------------------------------------------------------------------
// split GEMM inputs: 0=q,1=k,2=v,3=ctx
__device__ __nv_bfloat16 g_ahi[4][BB * SS * DD];
__device__ __nv_bfloat16 g_alo[4][BB * SS * DD];
// transposed split weights: 0=wq,1=wk,2=wv,3=wo ; layout [n][k]
__device__ __nv_bfloat16 g_wthi[4][DD * DD];
__device__ __nv_bfloat16 g_wtlo[4][DD * DD];
// split projection outputs (Q,K,V)
__device__ __nv_bfloat16 g_phi[3][BB * SS * DD];
__device__ __nv_bfloat16 g_plo[3][BB * SS * DD];

// ---------------------------------------------------------------------------
// PTX helpers (baseline ISA: ldmatrix + mma.sync + cp.async)
// ---------------------------------------------------------------------------
__device__ __forceinline__ uint32_t smem_u32(const void* p) {
    uint32_t a;
    asm("{ .reg .u64 t; cvta.to.shared.u64 t, %1; cvt.u32.u64 %0, t; }"
        : "=r"(a) : "l"(p));
    return a;
}

__device__ __forceinline__ void ldsm4(uint32_t addr, uint32_t r[4]) {
    asm volatile("ldmatrix.sync.aligned.m8n8.x4.shared.b16 {%0,%1,%2,%3}, [%4];"
                 : "=r"(r[0]), "=r"(r[1]), "=r"(r[2]), "=r"(r[3]) : "r"(addr));
}

__device__ __forceinline__ void ldsm2(uint32_t addr, uint32_t r[2]) {
    asm volatile("ldmatrix.sync.aligned.m8n8.x2.shared.b16 {%0,%1}, [%2];"
                 : "=r"(r[0]), "=r"(r[1]) : "r"(addr));
}

__device__ __forceinline__ void ldsm4t(uint32_t addr, uint32_t r[4]) {
    asm volatile("ldmatrix.sync.aligned.m8n8.x4.trans.shared.b16 {%0,%1,%2,%3}, [%4];"
                 : "=r"(r[0]), "=r"(r[1]), "=r"(r[2]), "=r"(r[3]) : "r"(addr));
}

__device__ __forceinline__ void mma16816(float c[4], const uint32_t a[4],
                                         const uint32_t b[2]) {
    asm volatile(
        "mma.sync.aligned.m16n8k16.row.col.f32.bf16.bf16.f32 "
        "{%0,%1,%2,%3}, {%4,%5,%6,%7}, {%8,%9}, {%0,%1,%2,%3};"
        : "+f"(c[0]), "+f"(c[1]), "+f"(c[2]), "+f"(c[3])
        : "r"(a[0]), "r"(a[1]), "r"(a[2]), "r"(a[3]), "r"(b[0]), "r"(b[1]));
}

__device__ __forceinline__ void cpa16(uint32_t s, const void* g) {
    asm volatile("cp.async.cg.shared.global [%0], [%1], 16;" :: "r"(s), "l"(g));
}
#define CP_COMMIT() asm volatile("cp.async.commit_group;" ::: "memory")
#define CP_WAIT(N) asm volatile("cp.async.wait_group %0;" :: "n"(N) : "memory")

__device__ __forceinline__ __nv_bfloat162 split2(float a, float b,
                                                 __nv_bfloat162& lo) {
    __nv_bfloat16 h0 = __float2bfloat16(a);
    __nv_bfloat16 h1 = __float2bfloat16(b);
    lo = __halves2bfloat162(__float2bfloat16(a - __bfloat162float(h0)),
                            __float2bfloat16(b - __bfloat162float(h1)));
    return __halves2bfloat162(h0, h1);
}

__device__ __forceinline__ void split2u(float a, float b, uint32_t& hi,
                                        uint32_t& lo) {
    __nv_bfloat162 l;
    __nv_bfloat162 h = split2(a, b, l);
    hi = *(uint32_t*)&h;
    lo = *(uint32_t*)&l;
}

// ---------------------------------------------------------------------------
// Split-precision conversion kernels (GEMM inputs)
// ---------------------------------------------------------------------------
__global__ void __launch_bounds__(256) split_qkv_kernel(const float* __restrict__ q,
                                                        const float* __restrict__ k,
                                                        const float* __restrict__ v) {
    const int z = blockIdx.y;
    const float* src = (z == 0) ? q : (z == 1) ? k : v;
    size_t i = (size_t)blockIdx.x * 256 + threadIdx.x;
    float4 x = ((const float4*)src)[i];
    __nv_bfloat162 l0, l1;
    __nv_bfloat162 h0 = split2(x.x, x.y, l0);
    __nv_bfloat162 h1 = split2(x.z, x.w, l1);
    ((__nv_bfloat162*)g_ahi[z])[2 * i + 0] = h0;
    ((__nv_bfloat162*)g_ahi[z])[2 * i + 1] = h1;
    ((__nv_bfloat162*)g_alo[z])[2 * i + 0] = l0;
    ((__nv_bfloat162*)g_alo[z])[2 * i + 1] = l1;
}

// Transpose + split weights: Wt[n][k] = W[k][n]
__global__ void __launch_bounds__(256) wt_split_kernel(const float* __restrict__ wq,
                                                       const float* __restrict__ wk,
                                                       const float* __restrict__ wv,
                                                       const float* __restrict__ wo) {
    const int z = blockIdx.z;
    const float* W = (z == 0) ? wq : (z == 1) ? wk : (z == 2) ? wv : wo;
    __shared__ float t[32][33];
    const int tx = threadIdx.x, ty = threadIdx.y;
    const int n0 = blockIdx.x * 32, k0 = blockIdx.y * 32;
#pragma unroll
    for (int i = 0; i < 4; i++)
        t[ty + 8 * i][tx] = W[(size_t)(k0 + ty + 8 * i) * DD + n0 + tx];
    __syncthreads();
#pragma unroll
    for (int i = 0; i < 4; i++) {
        int a = ty + 8 * i;
        float x = t[tx][a];
        __nv_bfloat16 h = __float2bfloat16(x);
        __nv_bfloat16 l = __float2bfloat16(x - __bfloat162float(h));
        g_wthi[z][(size_t)(n0 + a) * DD + k0 + tx] = h;
        g_wtlo[z][(size_t)(n0 + a) * DD + k0 + tx] = l;
    }
}

// ---------------------------------------------------------------------------
// mma.sync split-bf16 GEMM core: cp.async double-buffered, one barrier/iter
// (round-10 variant: best measured non-attn configuration, 345 us total)
// ---------------------------------------------------------------------------
#define SROW 40
#define GB_AH 0
#define GB_AL 10240
#define GB_BH 20480
#define GB_BL 30720
#define GBUF_SZ 40960
#define GEMM_SMEM_BYTES (2 * GBUF_SZ)

template <bool BF16OUT>
__device__ __forceinline__ void gemm_mma_core(const __nv_bfloat16* __restrict__ Ahi,
                                              const __nv_bfloat16* __restrict__ Alo,
                                              const __nv_bfloat16* __restrict__ Bhi,
                                              const __nv_bfloat16* __restrict__ Blo,
                                              const float* __restrict__ bias,
                                              float* __restrict__ Cf,
                                              __nv_bfloat16* __restrict__ Chi,
                                              __nv_bfloat16* __restrict__ Clo) {
    extern __shared__ char gsm[];
    const uint32_t smb = smem_u32(gsm);

    const int tid = threadIdx.x;
    const int wid = tid >> 5, lane = tid & 31;
    const int mbase = blockIdx.y * 128;
    const int nbase = blockIdx.x * 128;
    const int wM = (wid >> 2) * 64;
    const int wN = (wid & 3) * 32;

    const uint4* A4h = (const uint4*)Ahi;
    const uint4* A4l = (const uint4*)Alo;
    const uint4* B4h = (const uint4*)Bhi;
    const uint4* B4l = (const uint4*)Blo;

    float acc[4][4][4];
#pragma unroll
    for (int mt = 0; mt < 4; mt++)
#pragma unroll
        for (int nt = 0; nt < 4; nt++)
#pragma unroll
            for (int e = 0; e < 4; e++) acc[mt][nt][e] = 0.0f;

    const int r0 = tid >> 2;
    const int c0 = tid & 3;

    auto prefetch = [&](uint32_t buf, int kc) {
#pragma unroll
        for (int i = 0; i < 2; i++) {
            int r = r0 + i * 64;
            size_t ga = (size_t)(mbase + r) * 128 + kc * 4 + c0;
            size_t gb = (size_t)(nbase + r) * 128 + kc * 4 + c0;
            uint32_t so = (uint32_t)(r * (SROW * 2) + c0 * 16);
            cpa16(buf + GB_AH + so, &A4h[ga]);
            cpa16(buf + GB_AL + so, &A4l[ga]);
            cpa16(buf + GB_BH + so, &B4h[gb]);
            cpa16(buf + GB_BL + so, &B4l[gb]);
        }
    };

    prefetch(smb, 0);
    CP_COMMIT();

    for (int kc = 0; kc < 32; kc++) {
        CP_WAIT(0);
        __syncthreads();  // tile kc visible; prior readers of other buf done
        if (kc < 31) {
            prefetch(smb + ((kc + 1) & 1) * GBUF_SZ, kc + 1);
            CP_COMMIT();
        }
        const uint32_t buf = smb + (kc & 1) * GBUF_SZ;

#pragma unroll
        for (int s = 0; s < 2; s++) {
            uint32_t ah[4][4], al[4][4];
#pragma unroll
            for (int mt = 0; mt < 4; mt++) {
                uint32_t off = (uint32_t)((wM + mt * 16 + (lane & 15)) * (SROW * 2) +
                                          (s * 16 + (lane >> 4) * 8) * 2);
                ldsm4(buf + GB_AH + off, ah[mt]);
                ldsm4(buf + GB_AL + off, al[mt]);
            }
            uint32_t bh[4][2], bl[4][2];
#pragma unroll
            for (int nt = 0; nt < 4; nt++) {
                uint32_t off = (uint32_t)((wN + nt * 8 + (lane & 7)) * (SROW * 2) +
                                          (s * 16 + (lane & 8)) * 2);
                ldsm2(buf + GB_BH + off, bh[nt]);
                ldsm2(buf + GB_BL + off, bl[nt]);
            }
#pragma unroll
            for (int mt = 0; mt < 4; mt++)
#pragma unroll
                for (int nt = 0; nt < 4; nt++) {
                    mma16816(acc[mt][nt], ah[mt], bh[nt]);
                    mma16816(acc[mt][nt], ah[mt], bl[nt]);
                    mma16816(acc[mt][nt], al[mt], bh[nt]);
                }
        }
    }

#pragma unroll
    for (int mt = 0; mt < 4; mt++)
#pragma unroll
        for (int nt = 0; nt < 4; nt++) {
            int row = mbase + wM + mt * 16 + (lane >> 2);
            int col = nbase + wN + nt * 8 + (lane & 3) * 2;
            float b0 = bias[col], b1 = bias[col + 1];
            float v00 = acc[mt][nt][0] + b0, v01 = acc[mt][nt][1] + b1;
            float v10 = acc[mt][nt][2] + b0, v11 = acc[mt][nt][3] + b1;
            if (BF16OUT) {
                __nv_bfloat162 l0, l1;
                __nv_bfloat162 h0 = split2(v00, v01, l0);
                __nv_bfloat162 h1 = split2(v10, v11, l1);
                *(__nv_bfloat162*)&Chi[(size_t)row * 1024 + col] = h0;
                *(__nv_bfloat162*)&Clo[(size_t)row * 1024 + col] = l0;
                *(__nv_bfloat162*)&Chi[(size_t)(row + 8) * 1024 + col] = h1;
                *(__nv_bfloat162*)&Clo[(size_t)(row + 8) * 1024 + col] = l1;
            } else {
                *(float2*)&Cf[(size_t)row * 1024 + col] = make_float2(v00, v01);
                *(float2*)&Cf[(size_t)(row + 8) * 1024 + col] = make_float2(v10, v11);
            }
        }
}

__global__ void __launch_bounds__(256) mma_gemm_qkv_kernel(const float* __restrict__ bq,
                                                           const float* __restrict__ bk,
                                                           const float* __restrict__ bv) {
    const int z = blockIdx.z;
    const float* bias = (z == 0) ? bq : (z == 1) ? bk : bv;
    gemm_mma_core<true>(g_ahi[z], g_alo[z], g_wthi[z], g_wtlo[z], bias, nullptr,
                        g_phi[z], g_plo[z]);
}

__global__ void __launch_bounds__(256) mma_gemm_o_kernel(const float* __restrict__ bo,
                                                         float* __restrict__ out) {
    gemm_mma_core<false>(g_ahi[3], g_alo[3], g_wthi[3], g_wtlo[3], bo, out,
                         nullptr, nullptr);
}

// ---------------------------------------------------------------------------
// FA2-style HMMA attention — verbatim round-8 best (446 us incl. fused norm):
// BK=64, 2-stage cp.async, 2 barriers/iter, Q via smem ldsm,
// 2-MMA QK + 3-MMA PV, fp32 unnorm attn write + in-kernel re-read norm.
// ---------------------------------------------------------------------------
#define SRB 144                         // 64 bf16 + 8 pad per row
#define O_Q 0
#define BUF_BASE 18432
#define BUF_SZ 36864
#define BK_H 0
#define BK_L 9216
#define BV_H 18432
#define BV_L 27648
#define O_RS (BUF_BASE + 2 * BUF_SZ)
#define ATTN_SMEM_BYTES (O_RS + 512)

__device__ __forceinline__ void load_tile128(char* sm, uint32_t off,
                                             const __nv_bfloat16* g, int tid) {
    const uint4* g4 = (const uint4*)g;
#pragma unroll
    for (int i = 0; i < 4; i++) {
        int idx = tid + i * 256;
        int r = idx >> 3, c8 = idx & 7;
        *(uint4*)(sm + off + r * SRB + c8 * 16) = g4[(size_t)r * 128 + c8];
    }
}

__device__ __forceinline__ void prefetch_kv(uint32_t bufb,
                                            const __nv_bfloat16* Kh,
                                            const __nv_bfloat16* Kl,
                                            const __nv_bfloat16* Vh,
                                            const __nv_bfloat16* Vl, int tid) {
#pragma unroll
    for (int i = 0; i < 2; i++) {
        int idx = tid + i * 256;
        int r = idx >> 3, c8 = idx & 7;
        uint32_t so = (uint32_t)(r * SRB + c8 * 16);
        size_t go = (size_t)r * 1024 + c8 * 8;
        cpa16(bufb + BK_H + so, Kh + go);
        cpa16(bufb + BK_L + so, Kl + go);
        cpa16(bufb + BV_H + so, Vh + go);
        cpa16(bufb + BV_L + so, Vl + go);
    }
}

__global__ void __launch_bounds__(256, 2) attn_mma_kernel(
    const float* __restrict__ mask, float* __restrict__ attn, int write_attn) {
    extern __shared__ char sm[];
    const uint32_t smb = smem_u32(sm);
    float* rowsum = (float*)(sm + O_RS);

    const int tid = threadIdx.x;
    const int wid = tid >> 5, lane = tid & 31;
    const int bh = blockIdx.y;
    const int b = bh / HH, h = bh % HH;
    const int q0g = blockIdx.x * 128;
    const int qrow = wid * 16;

    const size_t hoff = (size_t)h * DEP;
    const float* maskrow = mask + (size_t)b * SS;

    // prefetch key tile 0
    {
        const size_t koff = (size_t)b * SS * DD + hoff;
        prefetch_kv(smb + BUF_BASE, g_phi[1] + koff, g_plo[1] + koff,
                    g_phi[2] + koff, g_plo[2] + koff, tid);
        CP_COMMIT();
    }

    // stage Q_hi and hoist A-fragments
    {
        const size_t qoff = ((size_t)b * SS + q0g) * DD + hoff;
        load_tile128(sm, O_Q, g_phi[0] + qoff, tid);
    }
    __syncthreads();

    uint32_t Qah[4][4];
#pragma unroll
    for (int s = 0; s < 4; s++) {
        uint32_t off = (uint32_t)((qrow + (lane & 15)) * SRB +
                                  (s * 16 + (lane >> 4) * 8) * 2);
        ldsm4(smb + O_Q + off, Qah[s]);
    }

    float ctx[8][4];
#pragma unroll
    for (int j = 0; j < 8; j++)
#pragma unroll
        for (int e = 0; e < 4; e++) ctx[j][e] = 0.0f;

    float rs0 = 0.0f, rs1 = 0.0f;

    for (int kt = 0; kt < 32; kt++) {
        if (kt < 31) {
            const size_t koff =
                ((size_t)b * SS + (kt + 1) * 64) * DD + hoff;
            uint32_t bufn = smb + BUF_BASE + ((kt + 1) & 1) * BUF_SZ;
            prefetch_kv(bufn, g_phi[1] + koff, g_plo[1] + koff,
                        g_phi[2] + koff, g_plo[2] + koff, tid);
            CP_COMMIT();
            CP_WAIT(1);
        } else {
            CP_WAIT(0);
        }
        __syncthreads();
        const uint32_t buf = smb + BUF_BASE + (kt & 1) * BUF_SZ;

        // ---- S = Q K^T over 64 keys (2-MMA: qh*kh + qh*kl) ----
        float accS[8][4];
#pragma unroll
        for (int j = 0; j < 8; j++)
#pragma unroll
            for (int e = 0; e < 4; e++) accS[j][e] = 0.0f;

#pragma unroll
        for (int s = 0; s < 4; s++) {
            const uint32_t brow = (lane & 7) + ((lane >> 4) << 3);
            const uint32_t bcol = (s * 16 + ((lane >> 3) & 1) * 8) * 2;
#pragma unroll
            for (int jp = 0; jp < 4; jp++) {
                uint32_t kb[4], kl[4];
                uint32_t off = (uint32_t)((16 * jp + brow) * SRB + bcol);
                ldsm4(buf + BK_H + off, kb);
                ldsm4(buf + BK_L + off, kl);
                mma16816(accS[2 * jp], Qah[s], kb);
                mma16816(accS[2 * jp], Qah[s], kl);
                mma16816(accS[2 * jp + 1], Qah[s], kb + 2);
                mma16816(accS[2 * jp + 1], Qah[s], kl + 2);
            }
        }

        // ---- interleaved: exp/split for 16-key group s, then PV MMAs ----
        const int rowl = qrow + (lane >> 2);
#pragma unroll
        for (int s = 0; s < 4; s++) {
            uint32_t pah[4], pal[4];
#pragma unroll
            for (int jj = 0; jj < 2; jj++) {
                const int j = 2 * s + jj;
                const int coll = 8 * j + (lane & 3) * 2;
                const int gcol = kt * 64 + coll;
                float m0 = __ldg(&maskrow[gcol]) * -1e9f;
                float m1 = __ldg(&maskrow[gcol + 1]) * -1e9f;
                float p00 = __expf(accS[j][0] * 0.125f + m0);
                float p01 = __expf(accS[j][1] * 0.125f + m1);
                float p10 = __expf(accS[j][2] * 0.125f + m0);
                float p11 = __expf(accS[j][3] * 0.125f + m1);
                rs0 += p00 + p01;
                rs1 += p10 + p11;
                if (write_attn) {
                    float* arow = attn + (size_t)bh * SS * SS +
                                  (size_t)(q0g + rowl) * SS + gcol;
                    *(float2*)arow = make_float2(p00, p01);
                    *(float2*)(arow + 8 * SS) = make_float2(p10, p11);
                }
                const int o = jj * 2;
                split2u(p00, p01, pah[o], pal[o]);
                split2u(p10, p11, pah[o + 1], pal[o + 1]);
            }
            const uint32_t vrow = 16 * s + (lane & 15);
#pragma unroll
            for (int jp = 0; jp < 4; jp++) {
                uint32_t vb[4], vl[4];
                uint32_t off = (uint32_t)(vrow * SRB +
                                          (16 * jp + ((lane >> 4) << 3)) * 2);
                ldsm4t(buf + BV_H + off, vb);
                ldsm4t(buf + BV_L + off, vl);
                mma16816(ctx[2 * jp], pah, vb);
                mma16816(ctx[2 * jp], pah, vl);
                mma16816(ctx[2 * jp], pal, vb);
                mma16816(ctx[2 * jp + 1], pah, vb + 2);
                mma16816(ctx[2 * jp + 1], pah, vl + 2);
                mma16816(ctx[2 * jp + 1], pal, vb + 2);
            }
        }
        __syncthreads();  // all warps done with buf before overwrite
    }

    // rowsums: warp-local reduce (each warp owns distinct rows)
    rs0 += __shfl_xor_sync(0xffffffffu, rs0, 1);
    rs0 += __shfl_xor_sync(0xffffffffu, rs0, 2);
    rs1 += __shfl_xor_sync(0xffffffffu, rs1, 1);
    rs1 += __shfl_xor_sync(0xffffffffu, rs1, 2);
    if ((lane & 3) == 0) {
        rowsum[qrow + (lane >> 2)] = rs0;
        rowsum[qrow + 8 + (lane >> 2)] = rs1;
    }
    __syncthreads();  // rowsum complete + attn writes visible block-wide

    // normalize ctx, split, store as O-GEMM input
    const int rowl = qrow + (lane >> 2);
    const float inv0 = 1.0f / rowsum[rowl];
    const float inv1 = 1.0f / rowsum[rowl + 8];
#pragma unroll
    for (int j = 0; j < 8; j++) {
        const int col = 8 * j + (lane & 3) * 2;
        size_t gi = ((size_t)b * SS + q0g + rowl) * DD + hoff + col;
        __nv_bfloat162 l0, l1;
        __nv_bfloat162 h0 = split2(ctx[j][0] * inv0, ctx[j][1] * inv0, l0);
        __nv_bfloat162 h1 = split2(ctx[j][2] * inv1, ctx[j][3] * inv1, l1);
        *(__nv_bfloat162*)&g_ahi[3][gi] = h0;
        *(__nv_bfloat162*)&g_alo[3][gi] = l0;
        *(__nv_bfloat162*)&g_ahi[3][gi + 8 * DD] = h1;
        *(__nv_bfloat162*)&g_alo[3][gi + 8 * DD] = l1;
    }

    // normalize this block's attn rows in-place (mostly L2-resident)
    if (write_attn) {
#pragma unroll 1
        for (int r = 0; r < 16; r++) {
            const int row = qrow + r;
            const float inv = 1.0f / rowsum[row];
            float4* arow = (float4*)(attn + (size_t)bh * SS * SS +
                                     (size_t)(q0g + row) * SS);
#pragma unroll
            for (int c = 0; c < 16; c++) {
                float4 v = arow[lane + c * 32];
                v.x *= inv;
                v.y *= inv;
                v.z *= inv;
                v.w *= inv;
                arow[lane + c * 32] = v;
            }
        }
    }
}

// ---------------------------------------------------------------------------
// kernel_launch
// ---------------------------------------------------------------------------
extern "C" void kernel_launch(void* const* d_in, const int* in_sizes, int n_in,
                              void* d_out, int out_size) {
    const float* q = (const float*)d_in[0];
    const float* k = (const float*)d_in[1];
    const float* v = (const float*)d_in[2];
    const float* mask = (const float*)d_in[3];
    const float* wq = (const float*)d_in[4];
    const float* bq = (const float*)d_in[5];
    const float* wk = (const float*)d_in[6];
    const float* bk = (const float*)d_in[7];
    const float* wv = (const float*)d_in[8];
    const float* bv = (const float*)d_in[9];
    const float* wo = (const float*)d_in[10];
    const float* bo = (const float*)d_in[11];

    float* out = (float*)d_out;
    const long long out_elems = (long long)BB * SS * DD;
    const long long need = out_elems + (long long)BB * HH * SS * SS;
    int write_attn = ((long long)out_size >= need) ? 1 : 0;
    float* attn = out + (size_t)out_elems;

    cudaFuncSetAttribute(attn_mma_kernel,
                         cudaFuncAttributeMaxDynamicSharedMemorySize,
                         ATTN_SMEM_BYTES);
    cudaFuncSetAttribute(mma_gemm_qkv_kernel,
                         cudaFuncAttributeMaxDynamicSharedMemorySize,
                         GEMM_SMEM_BYTES);
    cudaFuncSetAttribute(mma_gemm_o_kernel,
                         cudaFuncAttributeMaxDynamicSharedMemorySize,
                         GEMM_SMEM_BYTES);

    // 1. split inputs + weights
    split_qkv_kernel<<<dim3(BB * SS * DD / 4 / 256, 3), 256>>>(q, k, v);
    wt_split_kernel<<<dim3(32, 32, 4), dim3(32, 8)>>>(wq, wk, wv, wo);

    // 2. Q/K/V projections on HMMA (cp.async pipelined) -> split bf16 outputs
    mma_gemm_qkv_kernel<<<dim3(8, 32, 3), 256, GEMM_SMEM_BYTES>>>(bq, bk, bv);

    // 3. FA2-style HMMA attention (attn + in-kernel normalization + split ctx)
    attn_mma_kernel<<<dim3(SS / 128, BB * HH), 256, ATTN_SMEM_BYTES>>>(
        mask, attn, write_attn);

    // 4. output projection on HMMA
    mma_gemm_o_kernel<<<dim3(8, 32), 256, GEMM_SMEM_BYTES>>>(bo, out);
}